// round 16
// baseline (speedup 1.0000x reference)
#include <cuda_runtime.h>
#include <cstdint>

// Problem constants: pred/target [8,3,512,512] fp32, output scalar fp32.
#define BATCH   8
#define CHAN    3
#define HW      262144              // 512*512
#define NB      16                  // coarse bins
#define NFS     1024                // smem fine bins (atomic spread)
#define NFC     128                 // folded fine bins (reconstruction)
#define NSLICE  48                  // 2 tensors * 8 * 3
#define SPLITS  18                  // chunks per batch
#define CHUNK   14568               // ceil(HW/18) rounded to mult of 8
#define HIST_THREADS 1024

// Per-pixel fixed point via magic number: bits = __fmaf_rd(x,16384,2^23) has
// u = floor(x*16384) in its low 14 mantissa bits (x*16384 exact, RD = floor).
// Smem bin j10 = (bits>>4)&1023, stored sub-delta16 = bits & 15.
// Smem cell (32-bit): count in bits[18:32), sum(delta16) in bits[0:18).
//   per block per channel-tensor <= 14568 px: count < 2^14, sum <= 14568*15 < 2^18.
// Tail folds 8:1 to 128 bins: delta128 = (j10&7)*16 + delta16 (0..127);
//   per group cnt <= 14568 (fits), sd <= 14568*127 = 1.85M (fits uint).
// One int atomic per (slice, coarse bin): hist scaled x256 (<= 67M < 2^31).
// Integer accumulation -> bit-deterministic.  Last block (ticket) computes the
// loss in-kernel and self-cleans g_hist_i / g_ctr for the next graph replay.

__device__ int          g_hist_i[NSLICE][NB];  // fixed-point (x256) coarse hists
__device__ unsigned int g_ctr;                 // completion ticket (self-resetting)

// ---------------------------------------------------------------------------
// Single kernel: mask + fine histogram + in-block reconstruction + final loss.
// grid = BATCH * SPLITS = 144 blocks, 1024 threads, 32 KB smem (1 block/SM).
// ---------------------------------------------------------------------------
__device__ __forceinline__ void fine_add(unsigned int* sh, float x, bool m) {
    if (m) {
        unsigned int bits = __float_as_uint(__fmaf_rd(x, 16384.0f, 8388608.0f));
        atomicAdd(&sh[(bits >> 4) & (NFS - 1)], 0x40000u | (bits & 15u));
    }
}

__global__ __launch_bounds__(HIST_THREADS) void hist_kernel(const float* __restrict__ pred,
                                                            const float* __restrict__ target,
                                                            float* __restrict__ out) {
    __shared__ unsigned int sh[6][NFS];                  // 24 KB: [ct][bin]
    __shared__ float shw[NB][NFC];                       // 8 KB: Gaussian w(k, jc)
    __shared__ unsigned int s_amlast;
    int b     = blockIdx.x / SPLITS;
    int chunk = blockIdx.x % SPLITS;
    int tid   = threadIdx.x;

    // Build weight table in smem: 2 expf/thread (negligible MUFU density).
    #pragma unroll
    for (int i = 0; i < 2; i++) {
        int idx = tid + HIST_THREADS * i;                // 0..2047
        int k = idx >> 7;
        int j = idx & (NFC - 1);
        float d = ((float)j + 0.5f) * (1.0f / (float)NFC) - (float)k * (1.0f / 15.0f);
        shw[k][j] = expf(-128.0f * d * d);               // inv_two_sigma2 = 128
    }
    unsigned int* shf = &sh[0][0];
    #pragma unroll
    for (int j = tid; j < 6 * NFS; j += HIST_THREADS) shf[j] = 0u;
    __syncthreads();

    const float* tb = target + (size_t)b * CHAN * HW;
    const float* pb = pred   + (size_t)b * CHAN * HW;

    int start = chunk * CHUNK;
    int end   = min(start + CHUNK, HW);
    for (int i = start + tid * 4; i < end; i += HIST_THREADS * 4) {
        // front-batch all six 16B loads (MLP=6) before the atomic burst
        float4 t0 = *(const float4*)(tb + i);
        float4 t1 = *(const float4*)(tb + HW + i);
        float4 t2 = *(const float4*)(tb + 2 * HW + i);
        float4 p0 = *(const float4*)(pb + i);
        float4 p1 = *(const float4*)(pb + HW + i);
        float4 p2 = *(const float4*)(pb + 2 * HW + i);

        bool mx = (t0.x + t1.x) + t2.x > 1.2f;           // mean > 0.4
        bool my = (t0.y + t1.y) + t2.y > 1.2f;
        bool mz = (t0.z + t1.z) + t2.z > 1.2f;
        bool mw = (t0.w + t1.w) + t2.w > 1.2f;

        fine_add(sh[0], p0.x, mx); fine_add(sh[0], p0.y, my);
        fine_add(sh[0], p0.z, mz); fine_add(sh[0], p0.w, mw);
        fine_add(sh[1], p1.x, mx); fine_add(sh[1], p1.y, my);
        fine_add(sh[1], p1.z, mz); fine_add(sh[1], p1.w, mw);
        fine_add(sh[2], p2.x, mx); fine_add(sh[2], p2.y, my);
        fine_add(sh[2], p2.z, mz); fine_add(sh[2], p2.w, mw);
        fine_add(sh[3], t0.x, mx); fine_add(sh[3], t0.y, my);
        fine_add(sh[3], t0.z, mz); fine_add(sh[3], t0.w, mw);
        fine_add(sh[4], t1.x, mx); fine_add(sh[4], t1.y, my);
        fine_add(sh[4], t1.z, mz); fine_add(sh[4], t1.w, mw);
        fine_add(sh[5], t2.x, mx); fine_add(sh[5], t2.y, my);
        fine_add(sh[5], t2.z, mz); fine_add(sh[5], t2.w, mw);
    }
    __syncthreads();

    // Stage A: 8:1 fold.  Thread g (<768) reads its 8 raw words as 2x uint4,
    // then (after a barrier) writes compact float2 c[g] at the front of shf.
    float2 cval = make_float2(0.0f, 0.0f);
    if (tid < 6 * NFC) {
        const uint4* cell = (const uint4*)(shf + (tid << 3));
        uint4 lo = cell[0], hi = cell[1];
        unsigned int w8[8] = {lo.x, lo.y, lo.z, lo.w, hi.x, hi.y, hi.z, hi.w};
        unsigned int cnt = 0, sd = 0;
        #pragma unroll
        for (int r = 0; r < 8; r++) {
            unsigned int c = w8[r] >> 18;
            cnt += c;
            sd  += (w8[r] & 0x3FFFFu) + (c << 4) * (unsigned)r;  // delta128 accum
        }
        float n = (float)cnt;
        // sum(delta) ~= (sd + 0.5 n)/128 ; sdv = (sum(delta) - n/2) / NFC
        cval = make_float2(n, ((float)sd * 0.0078125f - n * 0.49609375f)
                              * (1.0f / (float)NFC));
    }
    __syncthreads();
    if (tid < 6 * NFC) ((float2*)shf)[tid] = cval;       // compact, conflict-free
    __syncthreads();

    // Stage B: 96 tasks (ct, k), 3 per warp; contract (n,sdv) with (w, w').
    int warp = tid >> 5;
    int lane = tid & 31;
    const float2* cbase = (const float2*)shf;
    #pragma unroll
    for (int it = 0; it < 3; it++) {
        int task = warp + 32 * it;                       // 0..95
        int ct = task >> 4;
        int k  = task & 15;
        float ck = (float)k * (1.0f / 15.0f);
        const float* wr = shw[k];
        float acc = 0.0f;
        #pragma unroll
        for (int j = 0; j < NFC / 32; j++) {             // 4 iterations
            int jc = lane + 32 * j;
            float2 nv = cbase[ct * NFC + jc];
            float w  = wr[jc];
            float d  = ((float)jc + 0.5f) * (1.0f / (float)NFC) - ck;
            acc = fmaf(nv.x, w, fmaf(nv.y, -256.0f * d * w, acc));
        }
        #pragma unroll
        for (int off = 16; off > 0; off >>= 1)
            acc += __shfl_xor_sync(0xffffffffu, acc, off);
        if (lane == 0) {
            int t  = ct >= 3;
            int ch = ct - t * 3;
            atomicAdd(&g_hist_i[t * 24 + b * 3 + ch][k], (int)rintf(acc * 256.0f));
        }
    }
    __syncthreads();

    // Ticket: last block computes the final loss (threadFenceReduction pattern).
    if (tid == 0) {
        __threadfence();
        unsigned int t = atomicAdd(&g_ctr, 1u);
        s_amlast = (t == (unsigned)(gridDim.x - 1));
    }
    __syncthreads();
    if (!s_amlast) return;

    // ---- last-block epilogue (parallel, fp32, deterministic) ----
    float* hv = (float*)shf;                             // reuse smem
    if (tid < NSLICE * NB) {                             // 768 threads: one per (s,k)
        float v = (float)g_hist_i[tid >> 4][tid & 15];   // x256 fixed point
        float sum = v;
        #pragma unroll
        for (int off = 8; off > 0; off >>= 1)            // per-slice sum (16-lane segs)
            sum += __shfl_xor_sync(0xffffffffu, sum, off, 16);
        // h = (v/256)/(sum/256 + 1e-7) = v/(sum + 256e-7)
        hv[tid] = v / (sum + 2.56e-5f);
    }
    __syncthreads();

    float a = 0.0f;
    if (tid < 384) {                                     // pred slice s vs target s+24
        a = fabsf(hv[tid] - hv[tid + 384]);
        #pragma unroll
        for (int off = 16; off > 0; off >>= 1)
            a += __shfl_xor_sync(0xffffffffu, a, off);
        if (lane == 0) hv[800 + warp] = a;               // 12 partials
    }
    __syncthreads();
    if (tid < 32) {
        float p = (tid < 12) ? hv[800 + tid] : 0.0f;
        #pragma unroll
        for (int off = 16; off > 0; off >>= 1)
            p += __shfl_xor_sync(0xffffffffu, p, off);
        if (tid == 0) *out = p * (1.0f / 384.0f);
    }
    __syncthreads();

    // self-clean for the next call (after all reads above)
    if (tid < NSLICE * NB) g_hist_i[tid >> 4][tid & 15] = 0;
    if (tid == 0) g_ctr = 0u;
}

// ---------------------------------------------------------------------------
extern "C" void kernel_launch(void* const* d_in, const int* in_sizes, int n_in,
                              void* d_out, int out_size) {
    const float* pred   = (const float*)d_in[0];
    const float* target = (const float*)d_in[1];
    float* out = (float*)d_out;

    hist_kernel<<<BATCH * SPLITS, HIST_THREADS>>>(pred, target, out);
}